// round 12
// baseline (speedup 1.0000x reference)
#include <cuda_runtime.h>

// HydraChannelMixer — GB300 sm_103a
// 16384 tiles of [C=32, D=128]; one tile per 256-thread block.
// All GEMMs fp32 scalar FMA with float4 weight loads (weights stay hot in L1).

#define BB 64
#define CC 32
#define PP 256
#define DD 128
#define RR 32
#define NT 256

__global__ __launch_bounds__(NT) void hydra_kernel(
    const float* __restrict__ x,
    const float* __restrict__ gamma,
    const float* __restrict__ beta,
    const float* __restrict__ W_down,   // [128][32]
    const float* __restrict__ b_down,   // [32]
    const float* __restrict__ W_q,      // [32][32]
    const float* __restrict__ W_k,      // [32][32]
    const float* __restrict__ W_v,      // [32][32]
    const float* __restrict__ W_cg,     // [32][32]
    const float* __restrict__ b_cg,     // [32]
    const float* __restrict__ W_up,     // [32][128]
    const float* __restrict__ b_up,     // [128]
    const float* __restrict__ Wg1,      // [257][32]
    const float* __restrict__ bg1,      // [32]
    const float* __restrict__ Wg2,      // [32][128]
    const float* __restrict__ bg2,      // [128]
    float* __restrict__ out)
{
    __shared__ float sh_h[CC][132];     // raw h tile, padded (132c+d banks distinct for 4 c's)
    __shared__ float sh_low[CC][36];    // h_low, pitch 36 -> 16B-aligned float4 rows, (4c+r) banks
    __shared__ float sh_qc[CC][36];     // Qn * cg
    __shared__ float sh_gamma[DD];
    __shared__ float sh_cS1[RR];        // sum_d gamma[d]*W_down[d][r]
    __shared__ float sh_cS2[RR];        // sum_d beta [d]*W_down[d][r]
    __shared__ float sh_mu[CC];
    __shared__ float sh_rstd[CC];
    __shared__ float sh_gin[260];       // gate_in [257]
    __shared__ float sh_gf[RR];         // global_feat
    __shared__ float sh_p8[8][RR];      // per-warp partials (gf; reused from cS1 partials)
    __shared__ float sh_p8b[8][RR];     // per-warp partials (g1; reused from cS2 partials)
    __shared__ float sh_g1[RR];
    __shared__ float sh_gate[DD];

    const int t    = threadIdx.x;
    const int bp   = blockIdx.x;
    const int b    = bp >> 8;           // P = 256
    const int p    = bp & 255;
    const int lane = t & 31;
    const int w    = t >> 5;

    const float4* x4 = (const float4*)x;
    const int xbase4 = (b * 8192 + p) * 32;   // float4 index of row (b*C+0, p); row c stride = 8192

    // ---- Phase A: load h tile (coalesced float4), gamma -> smem; cS1/cS2 partials ----
    #pragma unroll
    for (int i = 0; i < 4; i++) {
        int idx = i * NT + t;           // 0..1023 float4s
        int c = idx >> 5, v = idx & 31;
        float4 val = x4[xbase4 + c * 8192 + v];
        *(float4*)&sh_h[c][v * 4] = val;
    }
    if (t < DD) sh_gamma[t] = gamma[t];
    {
        int r = t & 31, ch = t >> 5;    // 8 chunks x 16 d
        float s1 = 0.f, s2 = 0.f;
        #pragma unroll 4
        for (int dd = 0; dd < 16; dd++) {
            int d = ch * 16 + dd;
            float wv = __ldg(W_down + d * RR + r);
            s1 = fmaf(__ldg(gamma + d), wv, s1);
            s2 = fmaf(__ldg(beta  + d), wv, s2);
        }
        sh_p8[ch][r]  = s1;
        sh_p8b[ch][r] = s2;
    }
    __syncthreads();

    // ---- Phase B/C: LN row stats (warps 0-3) + channel stats over C (warps 4-7) ----
    if (t < RR) {
        float s1 = 0.f, s2 = 0.f;
        #pragma unroll
        for (int ch = 0; ch < 8; ch++) { s1 += sh_p8[ch][t]; s2 += sh_p8b[ch][t]; }
        sh_cS1[t] = s1; sh_cS2[t] = s2;
    }
    if (w < 4) {
        #pragma unroll
        for (int q = 0; q < 8; q++) {
            int c = w * 8 + q;
            float s = 0.f, ss = 0.f;
            #pragma unroll
            for (int kk = 0; kk < 4; kk++) {
                float v = sh_h[c][lane + kk * 32];
                s += v; ss = fmaf(v, v, ss);
            }
            #pragma unroll
            for (int off = 16; off >= 1; off >>= 1) {
                s  += __shfl_xor_sync(0xffffffffu, s,  off);
                ss += __shfl_xor_sync(0xffffffffu, ss, off);
            }
            if (lane == 0) {
                float mu  = s * (1.f / 128.f);
                float var = ss * (1.f / 128.f) - mu * mu;
                sh_mu[c]   = mu;
                sh_rstd[c] = rsqrtf(var + 1e-5f);
            }
        }
    } else {
        int d = t - 128;
        float s = 0.f, ss = 0.f, sa = 0.f;
        #pragma unroll 8
        for (int c = 0; c < CC; c++) {
            float v = sh_h[c][d];
            s += v; ss = fmaf(v, v, ss); sa += fabsf(v);
        }
        sh_gin[d]        = (ss - s * s * (1.f / 32.f)) * (1.f / 31.f);  // ddof=1
        sh_gin[128 + d]  = sa * (1.f / 32.f);
        if (d == 0) sh_gin[256] = 0.501716659f;   // log(32)/log(1000)
    }
    __syncthreads();

    // ---- Phase D: h_low = LN(h) @ W_down + b_down   [32x32] ----
    {
        int c = t >> 3, rg = t & 7;
        float a0 = 0.f, a1 = 0.f, a2 = 0.f, a3 = 0.f;
        const float4* Wd4 = (const float4*)W_down + rg;
        #pragma unroll 4
        for (int d = 0; d < DD; d++) {
            float hv = sh_h[c][d] * sh_gamma[d];
            float4 wv = __ldg(Wd4 + d * 8);
            a0 = fmaf(hv, wv.x, a0);
            a1 = fmaf(hv, wv.y, a1);
            a2 = fmaf(hv, wv.z, a2);
            a3 = fmaf(hv, wv.w, a3);
        }
        float mu = sh_mu[c], rs = sh_rstd[c];
        int r0 = rg * 4;
        float4 o;
        o.x = fmaf(rs, a0 - mu * sh_cS1[r0 + 0], sh_cS2[r0 + 0] + __ldg(b_down + r0 + 0));
        o.y = fmaf(rs, a1 - mu * sh_cS1[r0 + 1], sh_cS2[r0 + 1] + __ldg(b_down + r0 + 1));
        o.z = fmaf(rs, a2 - mu * sh_cS1[r0 + 2], sh_cS2[r0 + 2] + __ldg(b_down + r0 + 2));
        o.w = fmaf(rs, a3 - mu * sh_cS1[r0 + 3], sh_cS2[r0 + 3] + __ldg(b_down + r0 + 3));
        *(float4*)&sh_low[c][r0] = o;
    }
    __syncthreads();

    // ---- Phase E: Q/K/V/cg GEMMs, l2norm, K*V global reduce, Qn*cg ----
    {
        int c = t >> 3, rg = t & 7;
        const float4* Wq4 = (const float4*)W_q  + rg;
        const float4* Wk4 = (const float4*)W_k  + rg;
        const float4* Wv4 = (const float4*)W_v  + rg;
        const float4* Wc4 = (const float4*)W_cg + rg;
        float q0=0,q1=0,q2=0,q3=0, k0=0,k1=0,k2=0,k3=0;
        float v0=0,v1=0,v2=0,v3=0, g0=0,g1=0,g2=0,g3=0;
        #pragma unroll 2
        for (int kk = 0; kk < RR; kk++) {
            float hv = sh_low[c][kk];
            float4 wq = __ldg(Wq4 + kk * 8);
            float4 wk = __ldg(Wk4 + kk * 8);
            float4 wv = __ldg(Wv4 + kk * 8);
            float4 wc = __ldg(Wc4 + kk * 8);
            q0 = fmaf(hv, wq.x, q0); q1 = fmaf(hv, wq.y, q1);
            q2 = fmaf(hv, wq.z, q2); q3 = fmaf(hv, wq.w, q3);
            k0 = fmaf(hv, wk.x, k0); k1 = fmaf(hv, wk.y, k1);
            k2 = fmaf(hv, wk.z, k2); k3 = fmaf(hv, wk.w, k3);
            v0 = fmaf(hv, wv.x, v0); v1 = fmaf(hv, wv.y, v1);
            v2 = fmaf(hv, wv.z, v2); v3 = fmaf(hv, wv.w, v3);
            g0 = fmaf(hv, wc.x, g0); g1 = fmaf(hv, wc.y, g1);
            g2 = fmaf(hv, wc.z, g2); g3 = fmaf(hv, wc.w, g3);
        }
        // row sumsq over the 8 lanes sharing c (aligned 8-lane groups)
        float sq = q0*q0 + q1*q1 + q2*q2 + q3*q3;
        float sk = k0*k0 + k1*k1 + k2*k2 + k3*k3;
        #pragma unroll
        for (int off = 1; off < 8; off <<= 1) {
            sq += __shfl_xor_sync(0xffffffffu, sq, off);
            sk += __shfl_xor_sync(0xffffffffu, sk, off);
        }
        float inq = 1.f / fmaxf(sqrtf(sq), 1e-12f);
        float ink = 1.f / fmaxf(sqrtf(sk), 1e-12f);
        int r0 = rg * 4;
        float4 bc = __ldg((const float4*)b_cg + rg);
        float c0 = 1.f / (1.f + __expf(-(g0 + bc.x)));
        float c1 = 1.f / (1.f + __expf(-(g1 + bc.y)));
        float c2 = 1.f / (1.f + __expf(-(g2 + bc.z)));
        float c3 = 1.f / (1.f + __expf(-(g3 + bc.w)));
        float4 qc;
        qc.x = q0 * inq * c0; qc.y = q1 * inq * c1;
        qc.z = q2 * inq * c2; qc.w = q3 * inq * c3;
        *(float4*)&sh_qc[c][r0] = qc;
        // K*V partial summed over the 4 c's in this warp
        float p0 = (k0 * ink) * v0, p1 = (k1 * ink) * v1;
        float p2 = (k2 * ink) * v2, p3 = (k3 * ink) * v3;
        #pragma unroll
        for (int off = 8; off <= 16; off <<= 1) {
            p0 += __shfl_xor_sync(0xffffffffu, p0, off);
            p1 += __shfl_xor_sync(0xffffffffu, p1, off);
            p2 += __shfl_xor_sync(0xffffffffu, p2, off);
            p3 += __shfl_xor_sync(0xffffffffu, p3, off);
        }
        if (lane < 8) {
            float4 pv = make_float4(p0, p1, p2, p3);
            *(float4*)&sh_p8[w][lane * 4] = pv;
        }
    }
    __syncthreads();

    // ---- Phase G1: gate_in @ Wg1 partials (all threads) + global_feat finalize ----
    {
        int j = t & 31, ch = t >> 5;
        int i0 = ch * 32;
        float s = 0.f;
        #pragma unroll 4
        for (int i = 0; i < 32; i++)
            s = fmaf(sh_gin[i0 + i], __ldcg(Wg1 + (i0 + i) * 32 + j), s);
        if (ch == 7)
            s = fmaf(sh_gin[256], __ldcg(Wg1 + 256 * 32 + j), s);
        sh_p8b[ch][j] = s;
    }
    if (t < RR) {
        float s = 0.f;
        #pragma unroll
        for (int ww = 0; ww < 8; ww++) s += sh_p8[ww][t];
        sh_gf[t] = s;
    }
    __syncthreads();

    if (t < RR) {
        float s = __ldg(bg1 + t);
        #pragma unroll
        for (int ww = 0; ww < 8; ww++) s += sh_p8b[ww][t];
        // exact GELU: 0.5*x*(1+erf(x/sqrt(2)))
        sh_g1[t] = 0.5f * s * (1.f + erff(s * 0.7071067811865475f));
    }
    __syncthreads();

    if (t < DD) {
        float s = __ldg(bg2 + t);
        #pragma unroll 8
        for (int j = 0; j < 32; j++)
            s = fmaf(sh_g1[j], __ldg(Wg2 + j * DD + t), s);
        sh_gate[t] = 1.f / (1.f + __expf(-s));
    }
    __syncthreads();

    // ---- Phase F: mixed = (Qn*cg*gf) @ W_up + b_up; out = h + gate*mixed ----
    {
        int c = t >> 3, dg = t & 7;
        const float4* Wu4 = (const float4*)W_up + dg * 4;
        float4 A[4];
        #pragma unroll
        for (int v = 0; v < 4; v++) A[v] = make_float4(0.f, 0.f, 0.f, 0.f);
        #pragma unroll 4
        for (int r = 0; r < RR; r++) {
            float av = sh_qc[c][r] * sh_gf[r];
            const float4* wr = Wu4 + r * 32;
            #pragma unroll
            for (int v = 0; v < 4; v++) {
                float4 wv = __ldg(wr + v);
                A[v].x = fmaf(av, wv.x, A[v].x);
                A[v].y = fmaf(av, wv.y, A[v].y);
                A[v].z = fmaf(av, wv.z, A[v].z);
                A[v].w = fmaf(av, wv.w, A[v].w);
            }
        }
        int d0 = dg * 16;
        float4* o4 = (float4*)out + ((b * CC + c) * PP + p) * 32 + (d0 >> 2);
        const float4* bu4 = (const float4*)b_up + (d0 >> 2);
        #pragma unroll
        for (int v = 0; v < 4; v++) {
            float4 hv = *(const float4*)&sh_h[c][d0 + v * 4];
            float4 gt = *(const float4*)&sh_gate[d0 + v * 4];
            float4 bu = __ldg(bu4 + v);
            float4 o;
            o.x = fmaf(gt.x, A[v].x + bu.x, hv.x);
            o.y = fmaf(gt.y, A[v].y + bu.y, hv.y);
            o.z = fmaf(gt.z, A[v].z + bu.z, hv.z);
            o.w = fmaf(gt.w, A[v].w + bu.w, hv.w);
            o4[v] = o;
        }
    }
}

extern "C" void kernel_launch(void* const* d_in, const int* in_sizes, int n_in,
                              void* d_out, int out_size)
{
    const float* x      = (const float*)d_in[0];
    const float* gamma  = (const float*)d_in[1];
    const float* beta   = (const float*)d_in[2];
    const float* W_down = (const float*)d_in[3];
    const float* b_down = (const float*)d_in[4];
    const float* W_q    = (const float*)d_in[5];
    const float* W_k    = (const float*)d_in[6];
    const float* W_v    = (const float*)d_in[7];
    const float* W_cg   = (const float*)d_in[8];
    const float* b_cg   = (const float*)d_in[9];
    const float* W_up   = (const float*)d_in[10];
    const float* b_up   = (const float*)d_in[11];
    const float* Wg1    = (const float*)d_in[12];
    const float* bg1    = (const float*)d_in[13];
    const float* Wg2    = (const float*)d_in[14];
    const float* bg2    = (const float*)d_in[15];

    hydra_kernel<<<BB * PP, NT>>>(x, gamma, beta, W_down, b_down,
                                  W_q, W_k, W_v, W_cg, b_cg,
                                  W_up, b_up, Wg1, bg1, Wg2, bg2,
                                  (float*)d_out);
}

// round 13
// speedup vs baseline: 1.6353x; 1.6353x over previous
#include <cuda_runtime.h>
#include <math.h>

// HydraChannelMixer — GB300 sm_103a, SMEM-staged weights + register-row tiling.
// 2 tiles [C=32, D=128] per 256-thread block, grid = 8192.

#define NT   256
#define GRID 8192

struct __align__(16) Tile {
    float h[32][132];    // raw h tile (pitch 132)
    float low[32][36];   // h_low, later overwritten by Qn*cg (pitch 36)
    float kv[32][36];    // Kn*V rows
    float gin[260];      // gate input [257]
    float mu[32];
    float rstd[32];
    float gf[32];        // global_feat
    float g1p[4][32];    // Wg1 partials
    float g1[32];
    float gate[144];     // gate, skewed layout: [q*36 + o]
    float pad[28];       // keeps sizeof(Tile) ≡ 16 words (mod 32) for bank separation
};

struct __align__(16) Smem {
    float Wd[128][32];   // gamma-folded W_down
    float We[32][148];   // [k][q*36+o] : q in {Q,K,V,CG}
    float Wu[32][148];   // [r][q*36+o] : W_up columns 32q+o
    float cS1[32];       // sum_d gamma*W_down
    float cS2f[32];      // sum_d beta*W_down + b_down
    Tile tile[2];
};

__global__ void __launch_bounds__(NT, 2) hydra_kernel(
    const float* __restrict__ x,
    const float* __restrict__ gamma,
    const float* __restrict__ beta,
    const float* __restrict__ W_down,
    const float* __restrict__ b_down,
    const float* __restrict__ W_q,
    const float* __restrict__ W_k,
    const float* __restrict__ W_v,
    const float* __restrict__ W_cg,
    const float* __restrict__ b_cg,
    const float* __restrict__ W_up,
    const float* __restrict__ b_up,
    const float* __restrict__ Wg1,
    const float* __restrict__ bg1,
    const float* __restrict__ Wg2,
    const float* __restrict__ bg2,
    float* __restrict__ out)
{
    extern __shared__ __align__(16) char smem_raw[];
    Smem& S = *reinterpret_cast<Smem*>(smem_raw);

    const int t    = threadIdx.x;
    const int lane = t & 31;
    const int w    = t >> 5;
    const unsigned FULL = 0xffffffffu;

    // cS partials parked in tile[].kv (unused until P3)
    float* cp1 = &S.tile[0].kv[0][0];
    float* cp2 = &S.tile[1].kv[0][0];

    // ================= P0: stage weights + both h tiles =================
    #pragma unroll
    for (int i = 0; i < 16; i++) {
        int idx = i * NT + t;
        int d = idx >> 5, r = idx & 31;
        S.Wd[d][r] = __ldg(gamma + d) * __ldg(W_down + idx);
    }
    {
        int o  = t & 31;
        int mq = (t >> 5) & 3;                 // uniform per warp
        const float* Wm = (mq == 0) ? W_q : (mq == 1) ? W_k : (mq == 2) ? W_v : W_cg;
        #pragma unroll
        for (int i = 0; i < 16; i++) {
            int k = i * 2 + (t >> 7);
            S.We[k][mq * 36 + o] = __ldg(Wm + k * 32 + o);
            S.Wu[k][mq * 36 + o] = __ldg(W_up + k * 128 + mq * 32 + o);
        }
    }
    {
        const float4* x4 = (const float4*)x;
        #pragma unroll
        for (int i = 0; i < 8; i++) {
            int g = i * NT + t;
            int tl = g >> 10, loc = g & 1023;
            int c = loc >> 5, v = loc & 31;
            int bp = blockIdx.x * 2 + tl;
            int b = bp >> 8, p = bp & 255;
            *(float4*)&S.tile[tl].h[c][v * 4] = x4[(b * 8192 + c * 256 + p) * 32 + v];
        }
    }
    {   // cS1/cS2 partials (pure LDG)
        int r = t & 31, ch = t >> 5;
        float s1 = 0.f, s2 = 0.f;
        #pragma unroll 4
        for (int dd = 0; dd < 16; dd++) {
            int d = ch * 16 + dd;
            float wv = __ldg(W_down + d * 32 + r);
            s1 = fmaf(__ldg(gamma + d), wv, s1);
            s2 = fmaf(__ldg(beta  + d), wv, s2);
        }
        cp1[ch * 32 + r] = s1;
        cp2[ch * 32 + r] = s2;
    }
    __syncthreads();

    // ================= P1: LN row stats + channel stats + cS finalize =================
    if (w < 4) {
        Tile& T = S.tile[w >> 1];
        int c0 = (w & 1) * 16;
        #pragma unroll 2
        for (int i = 0; i < 16; i++) {
            int c = c0 + i;
            float s = 0.f, ss = 0.f;
            #pragma unroll
            for (int u = 0; u < 4; u++) {
                float v = T.h[c][lane + 32 * u];
                s += v; ss = fmaf(v, v, ss);
            }
            #pragma unroll
            for (int off = 16; off >= 1; off >>= 1) {
                s  += __shfl_xor_sync(FULL, s,  off);
                ss += __shfl_xor_sync(FULL, ss, off);
            }
            if (lane == 0) {
                float mu  = s * 0.0078125f;
                float var = ss * 0.0078125f - mu * mu;
                T.mu[c]   = mu;
                T.rstd[c] = rsqrtf(var + 1e-5f);
            }
        }
    } else {
        int wi = w - 4;
        Tile& T = S.tile[wi >> 1];
        int d1 = (wi & 1) * 32 + lane;
        int d2 = d1 + 64;
        float s1=0.f, ss1=0.f, sa1=0.f, s2=0.f, ss2=0.f, sa2=0.f;
        #pragma unroll 8
        for (int c = 0; c < 32; c++) {
            float v1 = T.h[c][d1];
            float v2 = T.h[c][d2];
            s1 += v1; ss1 = fmaf(v1, v1, ss1); sa1 += fabsf(v1);
            s2 += v2; ss2 = fmaf(v2, v2, ss2); sa2 += fabsf(v2);
        }
        T.gin[d1]       = (ss1 - s1 * s1 * 0.03125f) * (1.f / 31.f);
        T.gin[128 + d1] = sa1 * 0.03125f;
        T.gin[d2]       = (ss2 - s2 * s2 * 0.03125f) * (1.f / 31.f);
        T.gin[128 + d2] = sa2 * 0.03125f;
        if ((wi & 1) == 0 && lane == 0) T.gin[256] = 0.501716659f;  // log(32)/log(1000)
    }
    if (t < 32) {
        float s = 0.f;
        #pragma unroll
        for (int ch = 0; ch < 8; ch++) s += cp1[ch * 32 + t];
        S.cS1[t] = s;
    } else if (t < 64) {
        int r = t - 32;
        float s = __ldg(b_down + r);
        #pragma unroll
        for (int ch = 0; ch < 8; ch++) s += cp2[ch * 32 + r];
        S.cS2f[r] = s;
    }
    __syncthreads();

    // ================= P2: down-proj for BOTH tiles (LN folded) =================
    {
        int c = t >> 3, rq = t & 7;
        float4 a0 = make_float4(0.f,0.f,0.f,0.f);
        float4 a1 = make_float4(0.f,0.f,0.f,0.f);
        #pragma unroll 4
        for (int d = 0; d < 128; d++) {
            float4 wv = *(const float4*)&S.Wd[d][rq * 4];
            float h0 = S.tile[0].h[c][d];
            float h1 = S.tile[1].h[c][d];
            a0.x = fmaf(h0, wv.x, a0.x); a0.y = fmaf(h0, wv.y, a0.y);
            a0.z = fmaf(h0, wv.z, a0.z); a0.w = fmaf(h0, wv.w, a0.w);
            a1.x = fmaf(h1, wv.x, a1.x); a1.y = fmaf(h1, wv.y, a1.y);
            a1.z = fmaf(h1, wv.z, a1.z); a1.w = fmaf(h1, wv.w, a1.w);
        }
        float4 cs1 = *(const float4*)&S.cS1[rq * 4];
        float4 cs2 = *(const float4*)&S.cS2f[rq * 4];
        {
            Tile& T = S.tile[0];
            float mu = T.mu[c], rs = T.rstd[c];
            float4 o;
            o.x = fmaf(rs, fmaf(-mu, cs1.x, a0.x), cs2.x);
            o.y = fmaf(rs, fmaf(-mu, cs1.y, a0.y), cs2.y);
            o.z = fmaf(rs, fmaf(-mu, cs1.z, a0.z), cs2.z);
            o.w = fmaf(rs, fmaf(-mu, cs1.w, a0.w), cs2.w);
            *(float4*)&T.low[c][rq * 4] = o;
        }
        {
            Tile& T = S.tile[1];
            float mu = T.mu[c], rs = T.rstd[c];
            float4 o;
            o.x = fmaf(rs, fmaf(-mu, cs1.x, a1.x), cs2.x);
            o.y = fmaf(rs, fmaf(-mu, cs1.y, a1.y), cs2.y);
            o.z = fmaf(rs, fmaf(-mu, cs1.z, a1.z), cs2.z);
            o.w = fmaf(rs, fmaf(-mu, cs1.w, a1.w), cs2.w);
            *(float4*)&T.low[c][rq * 4] = o;
        }
    }
    __syncthreads();

    // ================= P3: Q/K/V/CG — one full output row per thread =================
    {
        int c  = t >> 3;
        int qh = t & 7;
        int q  = qh & 3;       // 0=Q 1=K 2=V 3=CG
        int tl = qh >> 2;
        Tile& T = S.tile[tl];

        float acc[32];
        #pragma unroll
        for (int i = 0; i < 32; i++) acc[i] = 0.f;

        #pragma unroll 4
        for (int k = 0; k < 32; k++) {
            float hv = T.low[c][k];
            const float4* wr = (const float4*)&S.We[k][q * 36];
            #pragma unroll
            for (int j = 0; j < 8; j++) {
                float4 wv = wr[j];
                acc[4*j+0] = fmaf(hv, wv.x, acc[4*j+0]);
                acc[4*j+1] = fmaf(hv, wv.y, acc[4*j+1]);
                acc[4*j+2] = fmaf(hv, wv.z, acc[4*j+2]);
                acc[4*j+3] = fmaf(hv, wv.w, acc[4*j+3]);
            }
        }
        // in-thread l2norm for Q/K rows
        float s = 0.f;
        #pragma unroll
        for (int i = 0; i < 32; i++) s = fmaf(acc[i], acc[i], s);
        float rs  = 1.f / fmaxf(sqrtf(s), 1e-12f);
        float nrm = (q <= 1) ? rs : 1.f;
        #pragma unroll
        for (int i = 0; i < 32; i++) acc[i] *= nrm;

        int srck = (lane & ~3) | 1;   // K lane of this group
        int srcg = lane | 3;          // CG lane of this group
        #pragma unroll
        for (int j = 0; j < 8; j++) {   // Kn*V rows (stored by V lanes)
            float4 pv;
            pv.x = __shfl_sync(FULL, acc[4*j+0], srck) * acc[4*j+0];
            pv.y = __shfl_sync(FULL, acc[4*j+1], srck) * acc[4*j+1];
            pv.z = __shfl_sync(FULL, acc[4*j+2], srck) * acc[4*j+2];
            pv.w = __shfl_sync(FULL, acc[4*j+3], srck) * acc[4*j+3];
            if (q == 2) *(float4*)&T.kv[c][4*j] = pv;
        }
        #pragma unroll
        for (int j = 0; j < 8; j++) {   // cg sigmoid -> Q lanes store Qn*cg over low
            float4 bc = __ldg((const float4*)b_cg + j);
            float4 cg4;
            cg4.x = 1.f / (1.f + __expf(-(acc[4*j+0] + bc.x)));
            cg4.y = 1.f / (1.f + __expf(-(acc[4*j+1] + bc.y)));
            cg4.z = 1.f / (1.f + __expf(-(acc[4*j+2] + bc.z)));
            cg4.w = 1.f / (1.f + __expf(-(acc[4*j+3] + bc.w)));
            float4 qa;
            qa.x = acc[4*j+0] * __shfl_sync(FULL, cg4.x, srcg);
            qa.y = acc[4*j+1] * __shfl_sync(FULL, cg4.y, srcg);
            qa.z = acc[4*j+2] * __shfl_sync(FULL, cg4.z, srcg);
            qa.w = acc[4*j+3] * __shfl_sync(FULL, cg4.w, srcg);
            if (q == 0) *(float4*)&T.low[c][4*j] = qa;
        }
    }
    __syncthreads();

    // ================= P4: Wg1 partials + global_feat reduce =================
    {
        int tl = t >> 7, u = t & 127;
        Tile& T = S.tile[tl];
        int j = u & 31, ch = u >> 5;
        int i0 = ch * 64;
        float s = 0.f;
        #pragma unroll 4
        for (int i = 0; i < 64; i++)
            s = fmaf(T.gin[i0 + i], __ldg(Wg1 + (i0 + i) * 32 + j), s);
        if (ch == 3)
            s = fmaf(T.gin[256], __ldg(Wg1 + 256 * 32 + j), s);
        T.g1p[ch][j] = s;
        if (u < 32) {
            float g = 0.f;
            #pragma unroll 8
            for (int c = 0; c < 32; c++) g += T.kv[c][u];
            T.gf[u] = g;
        }
    }
    __syncthreads();

    // ================= P5: g1 (gelu) + prescale qa *= gf =================
    {
        int tl = t >> 7, u = t & 127;
        Tile& T = S.tile[tl];
        if (u < 32) {
            float s = __ldg(bg1 + u);
            #pragma unroll
            for (int ch = 0; ch < 4; ch++) s += T.g1p[ch][u];
            T.g1[u] = 0.5f * s * (1.f + erff(s * 0.7071067811865475f));
        }
        int c = u >> 2, rq = u & 3;
        float4 ga = *(const float4*)&T.gf[rq * 8];
        float4 gb = *(const float4*)&T.gf[rq * 8 + 4];
        float4 qa = *(const float4*)&T.low[c][rq * 8];
        float4 qb = *(const float4*)&T.low[c][rq * 8 + 4];
        qa.x *= ga.x; qa.y *= ga.y; qa.z *= ga.z; qa.w *= ga.w;
        qb.x *= gb.x; qb.y *= gb.y; qb.z *= gb.z; qb.w *= gb.w;
        *(float4*)&T.low[c][rq * 8]     = qa;
        *(float4*)&T.low[c][rq * 8 + 4] = qb;
    }
    __syncthreads();

    // ================= P6: gate2 (sigmoid) =================
    {
        int tl = t >> 7, u = t & 127;
        Tile& T = S.tile[tl];
        float s = __ldg(bg2 + u);
        #pragma unroll 8
        for (int j = 0; j < 32; j++)
            s = fmaf(T.g1[j], __ldg(Wg2 + j * 128 + u), s);
        T.gate[(u >> 5) * 36 + (u & 31)] = 1.f / (1.f + __expf(-s));  // skewed layout
    }
    __syncthreads();

    // ================= P7: up-proj + gated residual (into smem h) =================
    {
        int c  = t >> 3;
        int qh = t & 7;
        int q  = qh & 3;
        int tl = qh >> 2;
        Tile& T = S.tile[tl];

        float4 A[8];
        #pragma unroll
        for (int j = 0; j < 8; j++) A[j] = make_float4(0.f,0.f,0.f,0.f);

        #pragma unroll 4
        for (int r = 0; r < 32; r++) {
            float av = T.low[c][r];
            const float4* wr = (const float4*)&S.Wu[r][q * 36];
            #pragma unroll
            for (int j = 0; j < 8; j++) {
                float4 wv = wr[j];
                A[j].x = fmaf(av, wv.x, A[j].x);
                A[j].y = fmaf(av, wv.y, A[j].y);
                A[j].z = fmaf(av, wv.z, A[j].z);
                A[j].w = fmaf(av, wv.w, A[j].w);
            }
        }
        const float4* gt4 = (const float4*)&T.gate[q * 36];
        #pragma unroll
        for (int j = 0; j < 8; j++) {
            float4 hv = *(const float4*)&T.h[c][q * 32 + 4*j];
            float4 gt = gt4[j];
            float4 bu = __ldg((const float4*)b_up + q * 8 + j);
            float4 o;
            o.x = fmaf(gt.x, A[j].x + bu.x, hv.x);
            o.y = fmaf(gt.y, A[j].y + bu.y, hv.y);
            o.z = fmaf(gt.z, A[j].z + bu.z, hv.z);
            o.w = fmaf(gt.w, A[j].w + bu.w, hv.w);
            *(float4*)&T.h[c][q * 32 + 4*j] = o;
        }
    }
    __syncthreads();

    // ================= P8: coalesced store =================
    {
        float4* out4 = (float4*)out;
        #pragma unroll
        for (int i = 0; i < 8; i++) {
            int g = i * NT + t;
            int tl = g >> 10, loc = g & 1023;
            int c = loc >> 5, v = loc & 31;
            int bp = blockIdx.x * 2 + tl;
            int b = bp >> 8, p = bp & 255;
            out4[(b * 8192 + c * 256 + p) * 32 + v] = *(const float4*)&S.tile[tl].h[c][v * 4];
        }
    }
}

extern "C" void kernel_launch(void* const* d_in, const int* in_sizes, int n_in,
                              void* d_out, int out_size)
{
    const float* x      = (const float*)d_in[0];
    const float* gamma  = (const float*)d_in[1];
    const float* beta   = (const float*)d_in[2];
    const float* W_down = (const float*)d_in[3];
    const float* b_down = (const float*)d_in[4];
    const float* W_q    = (const float*)d_in[5];
    const float* W_k    = (const float*)d_in[6];
    const float* W_v    = (const float*)d_in[7];
    const float* W_cg   = (const float*)d_in[8];
    const float* b_cg   = (const float*)d_in[9];
    const float* W_up   = (const float*)d_in[10];
    const float* b_up   = (const float*)d_in[11];
    const float* Wg1    = (const float*)d_in[12];
    const float* bg1    = (const float*)d_in[13];
    const float* Wg2    = (const float*)d_in[14];
    const float* bg2    = (const float*)d_in[15];

    cudaFuncSetAttribute(hydra_kernel, cudaFuncAttributeMaxDynamicSharedMemorySize,
                         (int)sizeof(Smem));
    hydra_kernel<<<GRID, NT, sizeof(Smem)>>>(x, gamma, beta, W_down, b_down,
                                             W_q, W_k, W_v, W_cg, b_cg,
                                             W_up, b_up, Wg1, bg1, Wg2, bg2,
                                             (float*)d_out);
}